// round 16
// baseline (speedup 1.0000x reference)
#include <cuda_runtime.h>
#include <cuda_fp16.h>

// Vanilla tanh RNN: B=4096, T=2048, I=4, H=20, O=4.
// R16: DUAL-CHAIN single-warp-per-SMSP experiment. 4 warps/CTA (1/SMSP), grid 148,
// each warp runs TWO independent batch-chains whose instruction streams interleave
// so each chain's LDS/tanh/STS turnaround is covered by the other's fma work:
//   chain A = 3 batches, R12 layout (10 lanes/batch, 2 outputs/lane, lanes 0-29)
//   chain B = 4 batches, R14 layout (8 lanes/batch, 3/2 outputs/lane, all 32 lanes)
// 7 batches/warp, 148*4*7 = 4144 >= 4096 (ghost batches clamped, writes guarded).
// fp16x2/HFMA2 throughout, tanh.approx.f16x2, warp-private SMEM ping-pong per chain,
// syncwarp-free (per-warp in-order LSU + one compiler fence per step), PF=8 x rings.

#define B_TOTAL 4096
#define T_STEPS 2048
#define H_DIM   20
#define WARPS_CTA 4
#define CTA_THREADS (WARPS_CTA * 32)
#define GRID 148
#define PF 8
#define STRA 12                     // u32 stride per batch, chain A smem
#define STRB 12                     // u32 stride per batch, chain B smem

typedef unsigned int u32;
typedef unsigned long long u64;

__device__ __forceinline__ void unpack2(u64 v, float& lo, float& hi) {
    asm("mov.b64 {%0,%1}, %2;" : "=f"(lo), "=f"(hi) : "l"(v));
}
__device__ __forceinline__ u32 cvt2h(float hi, float lo) {
    u32 d; asm("cvt.rn.f16x2.f32 %0, %1, %2;" : "=r"(d) : "f"(hi), "f"(lo)); return d;
}
__device__ __forceinline__ u32 hfma2(u32 a, u32 b, u32 c) {
    u32 d; asm("fma.rn.f16x2 %0, %1, %2, %3;" : "=r"(d) : "r"(a), "r"(b), "r"(c)); return d;
}
__device__ __forceinline__ u32 hadd2(u32 a, u32 b) {
    u32 d; asm("add.rn.f16x2 %0, %1, %2;" : "=r"(d) : "r"(a), "r"(b)); return d;
}
__device__ __forceinline__ u32 prmt(u32 a, u32 b, u32 sel) {
    u32 d; asm("prmt.b32 %0, %1, %2, %3;" : "=r"(d) : "r"(a), "r"(b), "r"(sel)); return d;
}
__device__ __forceinline__ u32 tanh2(u32 a) {
    u32 d; asm("tanh.approx.f16x2 %0, %1;" : "=r"(d) : "r"(a)); return d;
}
__device__ __forceinline__ uint2 xld(const ulonglong2* __restrict__ p) {
    ulonglong2 v = __ldg(p);
    float x0, x1, x2, x3;
    unpack2(v.x, x0, x1);
    unpack2(v.y, x2, x3);
    return make_uint2(cvt2h(x1, x0), cvt2h(x3, x2));
}

// One DUAL step: chain A (R12 layout) + chain B (R14 layout), interleaved by ptxas.
__device__ __forceinline__ void rnn_step_dual(
    const u32* __restrict__ srcA, u32* __restrict__ dstA,
    const u32* __restrict__ srcB, u32* __restrict__ dstB,
    int gA, int sOffA, int gB, int rB, bool hstoreB,
    uint2 xhA, uint2 xhB,
    const u32* __restrict__ W0A, const u32* __restrict__ W1A,
    u32 WiA0, u32 WiA1, u32 WiA2, u32 WiA3, u32 seedA0, u32 seedA1,
    const u32 WaB[3][7], const u32 WbB[3][5], const u32* __restrict__ seedB)
{
    asm volatile("" ::: "memory");   // prior steps' STS before this step's LDS

    // ---- loads, both chains (issue early, latencies overlap) ----
    const u32* hbA = srcA + gA * STRA;
    uint4 aA = *reinterpret_cast<const uint4*>(hbA);
    uint4 aB = *reinterpret_cast<const uint4*>(hbA + 4);
    uint2 aC = *reinterpret_cast<const uint2*>(hbA + 8);

    const u32* hbB = srcB + gB * STRB;
    uint4 bA = *reinterpret_cast<const uint4*>(hbB);
    uint4 bB = *reinterpret_cast<const uint4*>(hbB + 4);
    uint2 bC = *reinterpret_cast<const uint2*>(hbB + 8);

    // ---- chain A compute (R12: 2 outputs, depth-6/6 chains) ----
    u32 Aa0 = hfma2(xhA.x, WiA0, seedA0);
    u32 Ab0 = hfma2(xhA.y, WiA1, 0u);
    u32 Aa1 = hfma2(xhA.x, WiA2, seedA1);
    u32 Ab1 = hfma2(xhA.y, WiA3, 0u);

    Aa0 = hfma2(aA.x, W0A[0], Aa0);  Ab0 = hfma2(aB.y, W0A[5], Ab0);
    Aa1 = hfma2(aA.x, W1A[0], Aa1);  Ab1 = hfma2(aB.y, W1A[5], Ab1);
    Aa0 = hfma2(aA.y, W0A[1], Aa0);  Ab0 = hfma2(aB.z, W0A[6], Ab0);
    Aa1 = hfma2(aA.y, W1A[1], Aa1);  Ab1 = hfma2(aB.z, W1A[6], Ab1);
    Aa0 = hfma2(aA.z, W0A[2], Aa0);  Ab0 = hfma2(aB.w, W0A[7], Ab0);
    Aa1 = hfma2(aA.z, W1A[2], Aa1);  Ab1 = hfma2(aB.w, W1A[7], Ab1);
    Aa0 = hfma2(aA.w, W0A[3], Aa0);  Ab0 = hfma2(aC.x, W0A[8], Ab0);
    Aa1 = hfma2(aA.w, W1A[3], Aa1);  Ab1 = hfma2(aC.x, W1A[8], Ab1);
    Aa0 = hfma2(aB.x, W0A[4], Aa0);  Ab0 = hfma2(aC.y, W0A[9], Ab0);
    Aa1 = hfma2(aB.x, W1A[4], Aa1);  Ab1 = hfma2(aC.y, W1A[9], Ab1);

    u32 AA = hadd2(Aa0, Ab0);
    u32 AB = hadd2(Aa1, Ab1);
    u32 AE = hadd2(prmt(AA, AB, 0x5410), prmt(AA, AB, 0x7632));
    u32 ATn = tanh2(AE);

    // ---- chain B compute (R14: 3 output-slots, depth-7/5 chains) ----
    u32 BAcc[3];
    #pragma unroll
    for (int i = 0; i < 3; i++) {
        u32 a = hfma2(xhB.x, WaB[i][0], seedB[i]);
        a = hfma2(xhB.y, WaB[i][1], a);
        a = hfma2(bA.x,  WaB[i][2], a);
        a = hfma2(bA.y,  WaB[i][3], a);
        a = hfma2(bA.z,  WaB[i][4], a);
        a = hfma2(bA.w,  WaB[i][5], a);
        a = hfma2(bC.x,  WaB[i][6], a);
        u32 b = hfma2(bB.x, WbB[i][0], 0u);
        b = hfma2(bB.y, WbB[i][1], b);
        b = hfma2(bB.z, WbB[i][2], b);
        b = hfma2(bB.w, WbB[i][3], b);
        b = hfma2(bC.y, WbB[i][4], b);
        BAcc[i] = hadd2(a, b);
    }
    u32 BE01 = hadd2(prmt(BAcc[0], BAcc[1], 0x5410), prmt(BAcc[0], BAcc[1], 0x7632));
    u32 BT01 = tanh2(BE01);
    u32 BE2  = hadd2(BAcc[2], prmt(BAcc[2], BAcc[2], 0x1032));
    u32 BT2  = tanh2(BE2);

    // ---- stores, both chains ----
    dstA[sOffA] = ATn;                               // A: word w_p (or scratch)
    u32* obB = dstB + gB * STRB;
    obB[rB] = BT01;                                  // B: word w_r
    if (hstoreB)
        reinterpret_cast<__half*>(obB + 8)[rB] =
            __ushort_as_half((unsigned short)(BT2 & 0xffffu));
}

__global__ void __launch_bounds__(CTA_THREADS, 1)
rnn_tanh_kernel(
    const float* __restrict__ x,     const float* __restrict__ h0,
    const float* __restrict__ W_ih,  const float* __restrict__ W_hh,
    const float* __restrict__ b_ih,  const float* __restrict__ b_hh,
    const float* __restrict__ fc_w,  const float* __restrict__ fc_b,
    float* __restrict__ out)
{
    __shared__ __align__(16) u32 smA[WARPS_CTA][2][40];
    __shared__ __align__(16) u32 smB[WARPS_CTA][2][48];

    const int lane = threadIdx.x & 31;
    const int w    = threadIdx.x >> 5;
    const int gw   = blockIdx.x * WARPS_CTA + w;
    const int base = gw * 7;
    if (base >= B_TOTAL + 48) return;                // never true; keeps shape

    // ---- chain A role (R12 layout) ----
    const bool liveA = (lane < 30);
    const int  gA    = liveA ? (lane / 10) : 2;
    const int  pA    = liveA ? (lane % 10) : (lane - 30);
    const int  bAid  = base + gA;
    const int  bAc   = (bAid < B_TOTAL) ? bAid : (B_TOTAL - 1);
    const int  o0A   = 2 * pA;
    const int  sOffA = liveA ? (gA * STRA + pA) : (38 + (lane - 30));

    // ---- chain B role (R14 layout) ----
    const int  gB    = lane >> 3;                    // 0..3
    const int  rB    = lane & 7;
    const bool hstoreB = (rB < 4);
    const int  bBid  = base + 3 + gB;
    const int  bBc   = (bBid < B_TOTAL) ? bBid : (B_TOTAL - 1);
    const int  jlo[10] = {0, 3, 6, 9, 12, 14, 16, 18, 2, 8};
    const int  jhi[10] = {1, 4, 7, 10, 13, 15, 17, 19, 5, 11};
    const int  oB0 = hstoreB ? (3 * rB)     : (2 * rB + 4);
    const int  oB1 = hstoreB ? (3 * rB + 1) : (2 * rB + 5);
    const int  oB2 = hstoreB ? (3 * rB + 2) : (2 * rB + 5);

    // ---- A weights ----
    u32 W0A[10], W1A[10];
    #pragma unroll
    for (int q = 0; q < 10; q++) {
        W0A[q] = cvt2h(__ldg(&W_hh[o0A * H_DIM + 2 * q + 1]),
                       __ldg(&W_hh[o0A * H_DIM + 2 * q]));
        W1A[q] = cvt2h(__ldg(&W_hh[(o0A + 1) * H_DIM + 2 * q + 1]),
                       __ldg(&W_hh[(o0A + 1) * H_DIM + 2 * q]));
    }
    const u32 WiA0 = cvt2h(__ldg(&W_ih[o0A * 4 + 1]), __ldg(&W_ih[o0A * 4 + 0]));
    const u32 WiA1 = cvt2h(__ldg(&W_ih[o0A * 4 + 3]), __ldg(&W_ih[o0A * 4 + 2]));
    const u32 WiA2 = cvt2h(__ldg(&W_ih[(o0A + 1) * 4 + 1]), __ldg(&W_ih[(o0A + 1) * 4 + 0]));
    const u32 WiA3 = cvt2h(__ldg(&W_ih[(o0A + 1) * 4 + 3]), __ldg(&W_ih[(o0A + 1) * 4 + 2]));
    const u32 seedA0 = cvt2h(0.f, __ldg(&b_ih[o0A])     + __ldg(&b_hh[o0A]));
    const u32 seedA1 = cvt2h(0.f, __ldg(&b_ih[o0A + 1]) + __ldg(&b_hh[o0A + 1]));

    // ---- B weights ----
    u32 WaB[3][7], WbB[3][5], seedB[3];
    const int ooB[3] = {oB0, oB1, oB2};
    #pragma unroll
    for (int i = 0; i < 3; i++) {
        const int o = ooB[i];
        WaB[i][0] = cvt2h(__ldg(&W_ih[o * 4 + 1]), __ldg(&W_ih[o * 4 + 0]));
        WaB[i][1] = cvt2h(__ldg(&W_ih[o * 4 + 3]), __ldg(&W_ih[o * 4 + 2]));
        #pragma unroll
        for (int q = 0; q < 4; q++)
            WaB[i][2 + q] = cvt2h(__ldg(&W_hh[o * H_DIM + jhi[q]]),
                                  __ldg(&W_hh[o * H_DIM + jlo[q]]));
        WaB[i][6] = cvt2h(__ldg(&W_hh[o * H_DIM + jhi[8]]),
                          __ldg(&W_hh[o * H_DIM + jlo[8]]));
        #pragma unroll
        for (int q = 0; q < 4; q++)
            WbB[i][q] = cvt2h(__ldg(&W_hh[o * H_DIM + jhi[4 + q]]),
                              __ldg(&W_hh[o * H_DIM + jlo[4 + q]]));
        WbB[i][4] = cvt2h(__ldg(&W_hh[o * H_DIM + jhi[9]]),
                          __ldg(&W_hh[o * H_DIM + jlo[9]]));
        seedB[i] = cvt2h(0.f, __ldg(&b_ih[o]) + __ldg(&b_hh[o]));
    }

    u32* A0 = &smA[w][0][0];  u32* A1 = &smA[w][1][0];
    u32* B0 = &smB[w][0][0];  u32* B1 = &smB[w][1][0];

    // ---- init h ----
    {
        const float2* h2 = reinterpret_cast<const float2*>(h0);
        float2 hv = __ldg(&h2[bAc * (H_DIM / 2) + pA]);
        A0[sOffA] = cvt2h(hv.y, hv.x);

        u32* obB = B0 + gB * STRB;
        obB[rB] = cvt2h(__ldg(&h0[bBc * H_DIM + oB1]), __ldg(&h0[bBc * H_DIM + oB0]));
        if (hstoreB)
            reinterpret_cast<__half*>(obB + 8)[rB] =
                __float2half(__ldg(&h0[bBc * H_DIM + oB2]));
    }
    __syncwarp();

    // ---- x rings (fp16x2-converted), one per chain ----
    const ulonglong2* xpA = reinterpret_cast<const ulonglong2*>(x) + (size_t)bAc * T_STEPS;
    const ulonglong2* xpB = reinterpret_cast<const ulonglong2*>(x) + (size_t)bBc * T_STEPS;
    uint2 xbA[PF], xbB[PF];
    #pragma unroll
    for (int q = 0; q < PF; q++) { xbA[q] = xld(&xpA[q]); xbB[q] = xld(&xpB[q]); }

    for (int t = 0; t < T_STEPS - PF; t += PF) {
        #pragma unroll
        for (int q = 0; q < PF; q++) {
            uint2 xhA = xbA[q], xhB = xbB[q];
            xbA[q] = xld(&xpA[t + q + PF]);
            xbB[q] = xld(&xpB[t + q + PF]);
            if (q & 1)
                rnn_step_dual(A1, A0, B1, B0, gA, sOffA, gB, rB, hstoreB, xhA, xhB,
                              W0A, W1A, WiA0, WiA1, WiA2, WiA3, seedA0, seedA1,
                              WaB, WbB, seedB);
            else
                rnn_step_dual(A0, A1, B0, B1, gA, sOffA, gB, rB, hstoreB, xhA, xhB,
                              W0A, W1A, WiA0, WiA1, WiA2, WiA3, seedA0, seedA1,
                              WaB, WbB, seedB);
        }
    }
    #pragma unroll
    for (int q = 0; q < PF; q++) {
        if (q & 1)
            rnn_step_dual(A1, A0, B1, B0, gA, sOffA, gB, rB, hstoreB, xbA[q], xbB[q],
                          W0A, W1A, WiA0, WiA1, WiA2, WiA3, seedA0, seedA1,
                          WaB, WbB, seedB);
        else
            rnn_step_dual(A0, A1, B0, B1, gA, sOffA, gB, rB, hstoreB, xbA[q], xbB[q],
                          W0A, W1A, WiA0, WiA1, WiA2, WiA3, seedA0, seedA1,
                          WaB, WbB, seedB);
    }

    // ---- heads (final h in ping buffers; T_STEPS even) ----
    __syncwarp();
    if (liveA && pA < 4 && bAid < B_TOTAL) {
        const u32* hb = A0 + gA * STRA;
        float acc = __ldg(&fc_b[pA]);
        #pragma unroll
        for (int q = 0; q < 10; q++) {
            float2 hv = __half22float2(*reinterpret_cast<const __half2*>(&hb[q]));
            acc = fmaf(hv.x, __ldg(&fc_w[pA * H_DIM + 2 * q]),     acc);
            acc = fmaf(hv.y, __ldg(&fc_w[pA * H_DIM + 2 * q + 1]), acc);
        }
        out[bAid * 4 + pA] = acc;
    }
    if (hstoreB && bBid < B_TOTAL) {
        const u32* hb = B0 + gB * STRB;
        float acc = __ldg(&fc_b[rB]);
        #pragma unroll
        for (int q = 0; q < 10; q++) {
            float2 hv = __half22float2(*reinterpret_cast<const __half2*>(&hb[q]));
            acc = fmaf(hv.x, __ldg(&fc_w[rB * H_DIM + jlo[q]]), acc);
            acc = fmaf(hv.y, __ldg(&fc_w[rB * H_DIM + jhi[q]]), acc);
        }
        out[bBid * 4 + rB] = acc;
    }
}

extern "C" void kernel_launch(void* const* d_in, const int* in_sizes, int n_in,
                              void* d_out, int out_size)
{
    const float* x    = (const float*)d_in[0];
    const float* h0   = (const float*)d_in[1];
    const float* W_ih = (const float*)d_in[2];
    const float* W_hh = (const float*)d_in[3];
    const float* b_ih = (const float*)d_in[4];
    const float* b_hh = (const float*)d_in[5];
    const float* fc_w = (const float*)d_in[6];
    const float* fc_b = (const float*)d_in[7];
    float* out = (float*)d_out;

    rnn_tanh_kernel<<<GRID, CTA_THREADS>>>(x, h0, W_ih, W_hh, b_ih, b_hh,
                                           fc_w, fc_b, out);
}

// round 17
// speedup vs baseline: 1.2177x; 1.2177x over previous
#include <cuda_runtime.h>
#include <cuda_fp16.h>

// Vanilla tanh RNN: B=4096, T=2048, I=4, H=20, O=4.
// R17: recurrence on the TENSOR pipe via warp-level mma.sync.m16n8k16.
// One warp owns 16 batches. Per step: D[16x24] = A[16x32] * B[32x24] + bias,
// where A cols 0..19 = h_{t-1}, cols 20..23 = x_t (input projection fused into
// the GEMM; W_ih occupies B rows 20..23), cols 24..31 = 0. Then tanh on D and
// rebuild A fragments -- the m16n8 D layout matches the m16k16 A layout
// position-for-position, so NO cross-lane data movement is needed: h lives in
// registers as MMA fragments forever. Zero SMEM, zero syncs in the loop.
// 128 CTAs x 2 warps = 256 warps x 16 batches = 4096 exactly.

#define T_STEPS 2048
#define H_DIM   20
#define GRID    128
#define PF      8

typedef unsigned int u32;

__device__ __forceinline__ u32 cvt2h(float hi, float lo) {
    u32 d; asm("cvt.rn.f16x2.f32 %0, %1, %2;" : "=r"(d) : "f"(hi), "f"(lo)); return d;
}
__device__ __forceinline__ u32 tanh2(u32 a) {
    u32 d; asm("tanh.approx.f16x2 %0, %1;" : "=r"(d) : "r"(a)); return d;
}

// D(m16n8,f32) = A(m16k16,f16,row) * B(k16n8,f16,col) + C(f32)
__device__ __forceinline__ void mma16816(
    float& d0, float& d1, float& d2, float& d3,
    u32 a0, u32 a1, u32 a2, u32 a3, u32 b0, u32 b1,
    float c0, float c1, float c2, float c3)
{
    asm("mma.sync.aligned.m16n8k16.row.col.f32.f16.f16.f32 "
        "{%0,%1,%2,%3},{%4,%5,%6,%7},{%8,%9},{%10,%11,%12,%13};"
        : "=f"(d0), "=f"(d1), "=f"(d2), "=f"(d3)
        : "r"(a0), "r"(a1), "r"(a2), "r"(a3), "r"(b0), "r"(b1),
          "f"(c0), "f"(c1), "f"(c2), "f"(c3));
}

// Combined weight matrix element: row o (output), col k in [0,32):
//   k<20 -> W_hh[o][k]; 20<=k<24 -> W_ih[o][k-20]; else 0. o>=20 -> 0.
__device__ __forceinline__ float wval(const float* __restrict__ W_hh,
                                      const float* __restrict__ W_ih,
                                      int o, int k)
{
    if (o >= H_DIM) return 0.0f;
    if (k < H_DIM) return __ldg(&W_hh[o * H_DIM + k]);
    if (k < H_DIM + 4) return __ldg(&W_ih[o * 4 + (k - H_DIM)]);
    return 0.0f;
}

// Load x[t] pair (2 floats at fixed offset) -> one fp16x2.
__device__ __forceinline__ u32 ldx2(const float* __restrict__ p) {
    float2 v = __ldg(reinterpret_cast<const float2*>(p));
    return cvt2h(v.y, v.x);
}

__global__ void __launch_bounds__(64, 1)
rnn_tanh_kernel(
    const float* __restrict__ x,     const float* __restrict__ h0,
    const float* __restrict__ W_ih,  const float* __restrict__ W_hh,
    const float* __restrict__ b_ih,  const float* __restrict__ b_hh,
    const float* __restrict__ fc_w,  const float* __restrict__ fc_b,
    float* __restrict__ out)
{
    const int lane = threadIdx.x & 31;
    const int w    = threadIdx.x >> 5;
    const int gp   = lane >> 2;          // groupID 0..7
    const int tg   = lane & 3;           // thread-in-group 0..3
    const int bb   = (blockIdx.x * 2 + w) * 16;
    const int b_lo = bb + gp;
    const int b_hi = bb + gp + 8;

    // ---- B fragments (weights), 2 k-tiles x 3 n-tiles x 2 regs ----
    u32 Bf[2][3][2];
    #pragma unroll
    for (int kt = 0; kt < 2; kt++)
        #pragma unroll
        for (int nt = 0; nt < 3; nt++) {
            const int n = nt * 8 + gp;
            const int kb = kt * 16 + 2 * tg;
            Bf[kt][nt][0] = cvt2h(wval(W_hh, W_ih, n, kb + 1),
                                  wval(W_hh, W_ih, n, kb));
            Bf[kt][nt][1] = cvt2h(wval(W_hh, W_ih, n, kb + 9),
                                  wval(W_hh, W_ih, n, kb + 8));
        }

    // ---- bias C fragments: c0,c1 = bias at cols nt*8 + 2tg, +1 (rows share) ----
    float cb0[3], cb1[3];
    #pragma unroll
    for (int nt = 0; nt < 3; nt++) {
        const int o0 = nt * 8 + 2 * tg;
        cb0[nt] = (o0     < H_DIM) ? (__ldg(&b_ih[o0])     + __ldg(&b_hh[o0]))     : 0.0f;
        cb1[nt] = (o0 + 1 < H_DIM) ? (__ldg(&b_ih[o0 + 1]) + __ldg(&b_hh[o0 + 1])) : 0.0f;
    }

    // ---- x ring pointers (this lane covers float pair c..c+1) ----
    const int c = (tg & 1) * 2;
    const float* xl = x + (size_t)b_lo * T_STEPS * 4 + c;
    const float* xh = x + (size_t)b_hi * T_STEPS * 4 + c;

    // ---- initial A fragments: h0 (cols 0..19) + x_0 (cols 20..23) ----
    u32 A00, A01, A02, A03, A10, A11;
    {
        const float* hl = h0 + (size_t)b_lo * H_DIM;
        const float* hh = h0 + (size_t)b_hi * H_DIM;
        A00 = cvt2h(__ldg(&hl[2 * tg + 1]), __ldg(&hl[2 * tg]));
        A01 = cvt2h(__ldg(&hh[2 * tg + 1]), __ldg(&hh[2 * tg]));
        A02 = cvt2h(__ldg(&hl[2 * tg + 9]), __ldg(&hl[2 * tg + 8]));
        A03 = cvt2h(__ldg(&hh[2 * tg + 9]), __ldg(&hh[2 * tg + 8]));
        if (tg < 2) {   // cols 16..19: h0[16+2tg, 17+2tg]
            A10 = cvt2h(__ldg(&hl[17 + 2 * tg]), __ldg(&hl[16 + 2 * tg]));
            A11 = cvt2h(__ldg(&hh[17 + 2 * tg]), __ldg(&hh[16 + 2 * tg]));
        } else {        // cols 20..23: x_0
            A10 = ldx2(xl);
            A11 = ldx2(xh);
        }
    }
    const u32 AZ = 0;   // A kt1 cols 24..31 = 0

    // ---- x prefetch ring: xr*[q] holds x_{t+1} for upcoming steps ----
    u32 xrl[PF], xrh[PF];
    #pragma unroll
    for (int q = 0; q < PF; q++) {
        xrl[q] = ldx2(xl + (size_t)(q + 1) * 4);
        xrh[q] = ldx2(xh + (size_t)(q + 1) * 4);
    }

    // ---- time loop: each iteration t consumes A=(h_{t-1}, x_t), produces h_t ----
    for (int tb = 0; tb < T_STEPS; tb += PF) {
        #pragma unroll
        for (int q = 0; q < PF; q++) {
            u32 xvl = xrl[q], xvh = xrh[q];          // x_{tb+q+1}
            int ni = tb + q + 1 + PF;
            ni = (ni < T_STEPS) ? ni : (T_STEPS - 1);
            xrl[q] = ldx2(xl + (size_t)ni * 4);
            xrh[q] = ldx2(xh + (size_t)ni * 4);

            float d0[4], d1[4], d2[4];
            mma16816(d0[0], d0[1], d0[2], d0[3], A00, A01, A02, A03,
                     Bf[0][0][0], Bf[0][0][1], cb0[0], cb1[0], cb0[0], cb1[0]);
            mma16816(d1[0], d1[1], d1[2], d1[3], A00, A01, A02, A03,
                     Bf[0][1][0], Bf[0][1][1], cb0[1], cb1[1], cb0[1], cb1[1]);
            mma16816(d2[0], d2[1], d2[2], d2[3], A00, A01, A02, A03,
                     Bf[0][2][0], Bf[0][2][1], cb0[2], cb1[2], cb0[2], cb1[2]);
            mma16816(d0[0], d0[1], d0[2], d0[3], A10, A11, AZ, AZ,
                     Bf[1][0][0], Bf[1][0][1], d0[0], d0[1], d0[2], d0[3]);
            mma16816(d1[0], d1[1], d1[2], d1[3], A10, A11, AZ, AZ,
                     Bf[1][1][0], Bf[1][1][1], d1[0], d1[1], d1[2], d1[3]);
            mma16816(d2[0], d2[1], d2[2], d2[3], A10, A11, AZ, AZ,
                     Bf[1][2][0], Bf[1][2][1], d2[0], d2[1], d2[2], d2[3]);

            // tanh + rebuild A (D layout == A layout, no lane movement)
            A00 = tanh2(cvt2h(d0[1], d0[0]));
            A01 = tanh2(cvt2h(d0[3], d0[2]));
            A02 = tanh2(cvt2h(d1[1], d1[0]));
            A03 = tanh2(cvt2h(d1[3], d1[2]));
            u32 t2a = tanh2(cvt2h(d2[1], d2[0]));
            u32 t2b = tanh2(cvt2h(d2[3], d2[2]));
            A10 = (tg < 2) ? t2a : xvl;              // cols 16-19 | x_{t+1}
            A11 = (tg < 2) ? t2b : xvh;
        }
    }

    // ---- head: out = h_last @ fc_w^T + fc_b, as one more MMA pair ----
    u32 Bh[2][2];
    #pragma unroll
    for (int kt = 0; kt < 2; kt++) {
        const int n = gp;                            // single n-tile, cols 0..7
        const int kb = kt * 16 + 2 * tg;
        float v0 = (n < 4 && kb     < H_DIM) ? __ldg(&fc_w[n * H_DIM + kb])     : 0.0f;
        float v1 = (n < 4 && kb + 1 < H_DIM) ? __ldg(&fc_w[n * H_DIM + kb + 1]) : 0.0f;
        float v2 = (n < 4 && kb + 8 < H_DIM) ? __ldg(&fc_w[n * H_DIM + kb + 8]) : 0.0f;
        float v3 = (n < 4 && kb + 9 < H_DIM) ? __ldg(&fc_w[n * H_DIM + kb + 9]) : 0.0f;
        Bh[kt][0] = cvt2h(v1, v0);
        Bh[kt][1] = cvt2h(v3, v2);
    }
    const float cf0 = (2 * tg     < 4) ? __ldg(&fc_b[2 * tg])     : 0.0f;
    const float cf1 = (2 * tg + 1 < 4) ? __ldg(&fc_b[2 * tg + 1]) : 0.0f;

    float hd[4];
    mma16816(hd[0], hd[1], hd[2], hd[3], A00, A01, A02, A03,
             Bh[0][0], Bh[0][1], cf0, cf1, cf0, cf1);
    mma16816(hd[0], hd[1], hd[2], hd[3], A10, A11, AZ, AZ,
             Bh[1][0], Bh[1][1], hd[0], hd[1], hd[2], hd[3]);

    if (tg < 2) {                                    // cols 2tg, 2tg+1 in [0,4)
        out[b_lo * 4 + 2 * tg]     = hd[0];
        out[b_lo * 4 + 2 * tg + 1] = hd[1];
        out[b_hi * 4 + 2 * tg]     = hd[2];
        out[b_hi * 4 + 2 * tg + 1] = hd[3];
    }
}

extern "C" void kernel_launch(void* const* d_in, const int* in_sizes, int n_in,
                              void* d_out, int out_size)
{
    const float* x    = (const float*)d_in[0];
    const float* h0   = (const float*)d_in[1];
    const float* W_ih = (const float*)d_in[2];
    const float* W_hh = (const float*)d_in[3];
    const float* b_ih = (const float*)d_in[4];
    const float* b_hh = (const float*)d_in[5];
    const float* fc_w = (const float*)d_in[6];
    const float* fc_b = (const float*)d_in[7];
    float* out = (float*)d_out;

    rnn_tanh_kernel<<<GRID, 64>>>(x, h0, W_ih, W_hh, b_ih, b_hh,
                                  fc_w, fc_b, out);
}